// round 4
// baseline (speedup 1.0000x reference)
#include <cuda_runtime.h>
#include <math.h>

#define NN 8192
#define KK 512
#define FF 64
#define SPLITJ 8
#define JCHUNK (NN / SPLITJ)   // 1024
#define BI 128
#define BJ 64
#define PSTRIDE 68             // p_s row stride (floats): 16B-aligned, 2-way-max banks

// ---------------- device scratch (no cudaMalloc allowed) ----------------
__device__ float g_h[(size_t)NN * FF];                 // 2 MB  : h = input @ W
__device__ float g_hl[NN];
__device__ float g_hr[NN];
__device__ float g_scalars[4];                         // [0]=max(hr) [1]=|W_ei| [2]=|W_si|
__device__ float g_acc[(size_t)SPLITJ * NN * FF];      // 16 MB : split-J partial numerators
__device__ float g_Z[SPLITJ * NN];                     // split-J partial denominators

// ---------------- packed f32x2 helpers (FFMA2 reachable only via PTX) ----------------
__device__ __forceinline__ unsigned long long pk2(float x, float y) {
    unsigned long long r;
    asm("mov.b64 %0, {%1,%2};" : "=l"(r) : "f"(x), "f"(y));
    return r;
}
__device__ __forceinline__ void fma2(unsigned long long& d, unsigned long long a,
                                     unsigned long long b) {
    asm("fma.rn.f32x2 %0, %1, %2, %0;" : "+l"(d) : "l"(a), "l"(b));
}
__device__ __forceinline__ float2 upk(unsigned long long v) {
    float2 f;
    asm("mov.b64 {%0,%1}, %2;" : "=f"(f.x), "=f"(f.y) : "l"(v));
    return f;
}

// =====================================================================
// A: h = input @ W   [8192,512]x[512,64]. 64x64 tile, 256 thr, 4x4/thr.
// =====================================================================
__global__ void __launch_bounds__(256) k_gemm_h(const float* __restrict__ X,
                                                const float* __restrict__ W) {
    __shared__ float xs[32][68];   // [k][row], padded
    const int t  = threadIdx.x;
    const int tx = t & 15;         // col quad: f = 4*tx..4*tx+3
    const int ty = t >> 4;         // row quad: i = 4*ty..4*ty+3
    const int i0 = blockIdx.x * 64;

    unsigned long long acc[4][2];
#pragma unroll
    for (int r = 0; r < 4; r++) { acc[r][0] = 0ULL; acc[r][1] = 0ULL; }

    for (int c0 = 0; c0 < KK; c0 += 32) {
#pragma unroll
        for (int q = 0; q < 8; q++) {
            int lin = t + 256 * q;            // 0..2047
            int row = lin >> 5;               // 0..63
            int kk  = lin & 31;
            xs[kk][row] = X[(size_t)(i0 + row) * KK + c0 + kk];
        }
        __syncthreads();
#pragma unroll
        for (int kk = 0; kk < 32; kk++) {
            float4 w4 = *(const float4*)&W[(size_t)(c0 + kk) * FF + 4 * tx];
            unsigned long long w01 = pk2(w4.x, w4.y);
            unsigned long long w23 = pk2(w4.z, w4.w);
            float4 a4 = *(const float4*)&xs[kk][4 * ty];
            float av[4] = {a4.x, a4.y, a4.z, a4.w};
#pragma unroll
            for (int r = 0; r < 4; r++) {
                unsigned long long ar = pk2(av[r], av[r]);
                fma2(acc[r][0], ar, w01);
                fma2(acc[r][1], ar, w23);
            }
        }
        __syncthreads();
    }
#pragma unroll
    for (int r = 0; r < 4; r++) {
        float2 lo = upk(acc[r][0]);
        float2 hi = upk(acc[r][1]);
        *(float4*)&g_h[(size_t)(i0 + 4 * ty + r) * FF + 4 * tx] =
            make_float4(lo.x, lo.y, hi.x, hi.y);
    }
}

// =====================================================================
// B: hl = h @ a[:64], hr = h @ a[64:128]
// =====================================================================
__global__ void __launch_bounds__(256) k_hlr(const float* __restrict__ a) {
    __shared__ float a1s[FF], a2s[FF];
    const int t = threadIdx.x;
    if (t < FF)            a1s[t]      = a[t];
    else if (t < 2 * FF)   a2s[t - FF] = a[t];
    __syncthreads();
    const int row = blockIdx.x * 256 + t;
    float s1 = 0.f, s2 = 0.f;
#pragma unroll
    for (int q = 0; q < 16; q++) {
        float4 h4 = *(const float4*)&g_h[(size_t)row * FF + 4 * q];
        s1 = fmaf(h4.x, a1s[4 * q + 0], s1);
        s1 = fmaf(h4.y, a1s[4 * q + 1], s1);
        s1 = fmaf(h4.z, a1s[4 * q + 2], s1);
        s1 = fmaf(h4.w, a1s[4 * q + 3], s1);
        s2 = fmaf(h4.x, a2s[4 * q + 0], s2);
        s2 = fmaf(h4.y, a2s[4 * q + 1], s2);
        s2 = fmaf(h4.z, a2s[4 * q + 2], s2);
        s2 = fmaf(h4.w, a2s[4 * q + 3], s2);
    }
    g_hl[row] = s1;
    g_hr[row] = s2;
}

// =====================================================================
// C: scalars — max_j hr_j, |W_ei|, |W_si|
// =====================================================================
__global__ void k_scalars(const float* __restrict__ Wsi, const float* __restrict__ Wei) {
    __shared__ float red[256];
    const int t = threadIdx.x;
    float m = -3.4e38f;
    for (int i = t; i < NN; i += 256) m = fmaxf(m, g_hr[i]);
    red[t] = m;
    __syncthreads();
    for (int s = 128; s > 0; s >>= 1) {
        if (t < s) red[t] = fmaxf(red[t], red[t + s]);
        __syncthreads();
    }
    if (t == 0) {
        g_scalars[0] = red[0];
        g_scalars[1] = fabsf(Wei[0]);
        g_scalars[2] = fabsf(Wsi[0]);
    }
}

// =====================================================================
// D: fused masked-softmax-numerator @ h, split over J.
// CTA = 128 rows x 1024 cols (16 tiles of 64 j). 256 threads, 2 CTAs/SM.
// Phase 1: p[i][j] = adj>0 ? exp(|Wei|*lrelu(hl_i+hr_j) + |Wsi|*ad - m_i) : 0
// Phase 2: acc[i][f] += p*h[j][f] (packed f32x2), z[i] += p.
// =====================================================================
__global__ void __launch_bounds__(256, 2) k_attn(const float* __restrict__ adj_ad,
                                                 const int* __restrict__ adj) {
    extern __shared__ float smem[];
    float* p_s  = smem;                          // BI * PSTRIDE = 8704 floats
    float* h_s  = p_s + BI * PSTRIDE;            // BJ * FF      = 4096 floats
    float* m_s  = h_s + BJ * FF;                 // BI
    float* hl_s = m_s + BI;                      // BI

    const int t     = threadIdx.x;
    const int i0    = blockIdx.x * BI;
    const int split = blockIdx.y;
    const int j0b   = split * JCHUNK;

    const float hrmax = g_scalars[0];
    const float wei   = g_scalars[1];
    const float wsi   = g_scalars[2];

    if (t < BI) {
        float hl = g_hl[i0 + t];
        hl_s[t] = hl;
        float s  = hl + hrmax;
        float lr = fmaxf(s, 0.2f * s);
        m_s[t] = fmaf(wei, lr, wsi);             // upper bound on row-i logits
    }
    __syncthreads();

    const int tx1 = t & 63, ty1 = t >> 6;        // phase-1 map (j, row-group)
    const int tx2 = t & 7,  ty2 = t >> 3;        // phase-2 map (f-octet, 4-row group)

    unsigned long long acc[4][4];
#pragma unroll
    for (int r = 0; r < 4; r++)
#pragma unroll
        for (int c = 0; c < 4; c++) acc[r][c] = 0ULL;
    float z[4] = {0.f, 0.f, 0.f, 0.f};

    for (int jt = 0; jt < JCHUNK / BJ; jt++) {
        const int j0 = j0b + jt * BJ;

        // --- load h tile [64 j][64 f] ---
#pragma unroll
        for (int q = 0; q < 4; q++) {
            int lin = t + 256 * q;               // float4 index 0..1023
            *(float4*)&h_s[lin * 4] = *(const float4*)&g_h[(size_t)j0 * FF + lin * 4];
        }

        // --- phase 1: p tile ---
        {
            const float hr = g_hr[j0 + tx1];
            const float* adp = adj_ad + (size_t)(i0 + ty1) * NN + (j0 + tx1);
            const int*   ajp = adj    + (size_t)(i0 + ty1) * NN + (j0 + tx1);
#pragma unroll 4
            for (int k = 0; k < 32; k++) {
                const int row = 4 * k + ty1;
                float ad = adp[(size_t)(4 * k) * NN];
                int   aj = ajp[(size_t)(4 * k) * NN];
                float s  = hl_s[row] + hr;
                float lr = fmaxf(s, 0.2f * s);
                float e  = fmaf(wei, lr, wsi * ad) - m_s[row];
                float p  = (aj > 0) ? __expf(e) : 0.0f;
                p_s[row * PSTRIDE + tx1] = p;
            }
        }
        __syncthreads();

        // --- phase 2: acc += p @ h ---
#pragma unroll
        for (int jb = 0; jb < BJ / 4; jb++) {
            float4 pr[4];
#pragma unroll
            for (int r = 0; r < 4; r++)
                pr[r] = *(const float4*)&p_s[(4 * ty2 + r) * PSTRIDE + 4 * jb];
#pragma unroll
            for (int jj = 0; jj < 4; jj++) {
                const float* hrow = &h_s[(4 * jb + jj) * FF + 8 * tx2];
                float4 ha = *(const float4*)hrow;
                float4 hb = *(const float4*)(hrow + 4);
                unsigned long long h01 = pk2(ha.x, ha.y);
                unsigned long long h23 = pk2(ha.z, ha.w);
                unsigned long long h45 = pk2(hb.x, hb.y);
                unsigned long long h67 = pk2(hb.z, hb.w);
#pragma unroll
                for (int r = 0; r < 4; r++) {
                    float pv = (jj == 0) ? pr[r].x :
                               (jj == 1) ? pr[r].y :
                               (jj == 2) ? pr[r].z : pr[r].w;
                    unsigned long long pp = pk2(pv, pv);
                    fma2(acc[r][0], pp, h01);
                    fma2(acc[r][1], pp, h23);
                    fma2(acc[r][2], pp, h45);
                    fma2(acc[r][3], pp, h67);
                    z[r] += pv;
                }
            }
        }
        __syncthreads();   // protect p_s/h_s before next tile overwrites
    }

    // --- writeout partials ---
#pragma unroll
    for (int r = 0; r < 4; r++) {
        const int row = i0 + 4 * ty2 + r;
        const size_t base = ((size_t)split * NN + row) * FF + 8 * tx2;
        float2 v0 = upk(acc[r][0]);
        float2 v1 = upk(acc[r][1]);
        float2 v2 = upk(acc[r][2]);
        float2 v3 = upk(acc[r][3]);
        *(float4*)&g_acc[base]     = make_float4(v0.x, v0.y, v1.x, v1.y);
        *(float4*)&g_acc[base + 4] = make_float4(v2.x, v2.y, v3.x, v3.y);
        if (tx2 == 0) g_Z[split * NN + row] = z[r];
    }
}

// =====================================================================
// E: combine splits, normalize, ELU
// =====================================================================
__global__ void __launch_bounds__(256) k_combine(float* __restrict__ out) {
    const int idx = blockIdx.x * 256 + threadIdx.x;   // = i*FF + f
    const int i   = idx >> 6;
    float num = 0.f, den = 0.f;
#pragma unroll
    for (int s = 0; s < SPLITJ; s++) {
        num += g_acc[(size_t)s * NN * FF + idx];
        den += g_Z[s * NN + i];
    }
    float r = num / den;
    out[idx] = (r > 0.0f) ? r : expm1f(r);
}

// =====================================================================
extern "C" void kernel_launch(void* const* d_in, const int* in_sizes, int n_in,
                              void* d_out, int out_size) {
    (void)in_sizes; (void)n_in; (void)out_size;
    const float* input  = (const float*)d_in[0];
    const float* W      = (const float*)d_in[1];
    const float* a      = (const float*)d_in[2];
    const float* W_si   = (const float*)d_in[3];
    const float* W_ei   = (const float*)d_in[4];
    const float* adj_ad = (const float*)d_in[5];
    const int*   adj    = (const int*)d_in[6];
    float* out = (float*)d_out;

    const int SMEM_D = (BI * PSTRIDE + BJ * FF + 2 * BI) * (int)sizeof(float); // 52224 B
    cudaFuncSetAttribute(k_attn, cudaFuncAttributeMaxDynamicSharedMemorySize, SMEM_D);

    k_gemm_h<<<NN / 64, 256>>>(input, W);
    k_hlr<<<NN / 256, 256>>>(a);
    k_scalars<<<1, 256>>>(W_si, W_ei);
    k_attn<<<dim3(NN / BI, SPLITJ), 256, SMEM_D>>>(adj_ad, adj);
    k_combine<<<NN * FF / 256, 256>>>(out);
}

// round 5
// speedup vs baseline: 1.4514x; 1.4514x over previous
#include <cuda_runtime.h>
#include <math.h>

#define NN 8192
#define KK 512
#define FF 64
#define SPLITJ 8
#define JCHUNK (NN / SPLITJ)   // 1024
#define BI 64
#define BJ 64
#define NTILES (JCHUNK / BJ)   // 16
#define PSTRIDE 68

// ---------------- device scratch (no cudaMalloc allowed) ----------------
__device__ float g_h[(size_t)NN * FF];                 // 2 MB
__device__ float g_hl[NN];
__device__ float g_hr[NN];
__device__ float g_scalars[4];                         // [0]=max(hr) [1]=|W_ei| [2]=|W_si|
__device__ float g_acc[(size_t)SPLITJ * NN * FF];      // 16 MB
__device__ float g_Z[SPLITJ * NN];

// ---------------- PTX helpers ----------------
__device__ __forceinline__ unsigned long long pk2(float x, float y) {
    unsigned long long r;
    asm("mov.b64 %0, {%1,%2};" : "=l"(r) : "f"(x), "f"(y));
    return r;
}
__device__ __forceinline__ void fma2(unsigned long long& d, unsigned long long a,
                                     unsigned long long b) {
    asm("fma.rn.f32x2 %0, %1, %2, %0;" : "+l"(d) : "l"(a), "l"(b));
}
__device__ __forceinline__ float2 upk(unsigned long long v) {
    float2 f;
    asm("mov.b64 {%0,%1}, %2;" : "=f"(f.x), "=f"(f.y) : "l"(v));
    return f;
}
// 128-bit shared load directly into two packed-f32x2 operands (no repack movs)
__device__ __forceinline__ void lds_u64x2(unsigned long long& a, unsigned long long& b,
                                          const float* p) {
    asm volatile("ld.shared.v2.u64 {%0,%1}, [%2];"
                 : "=l"(a), "=l"(b)
                 : "r"((unsigned)__cvta_generic_to_shared(p)));
}
__device__ __forceinline__ void cpasync16(void* dst_smem, const void* src) {
    asm volatile("cp.async.cg.shared.global [%0], [%1], 16;"
                 :: "r"((unsigned)__cvta_generic_to_shared(dst_smem)), "l"(src));
}
#define CP_COMMIT() asm volatile("cp.async.commit_group;" ::: "memory")
#define CP_WAIT1()  asm volatile("cp.async.wait_group 1;" ::: "memory")
#define CP_WAITALL() asm volatile("cp.async.wait_all;" ::: "memory")

// =====================================================================
// A: h = input @ W   [8192,512]x[512,64]. 64x64 tile, 256 thr, 4x4/thr.
// =====================================================================
__global__ void __launch_bounds__(256) k_gemm_h(const float* __restrict__ X,
                                                const float* __restrict__ W) {
    __shared__ float xs[32][68];
    const int t  = threadIdx.x;
    const int tx = t & 15;
    const int ty = t >> 4;
    const int i0 = blockIdx.x * 64;

    unsigned long long acc[4][2];
#pragma unroll
    for (int r = 0; r < 4; r++) { acc[r][0] = 0ULL; acc[r][1] = 0ULL; }

    for (int c0 = 0; c0 < KK; c0 += 32) {
#pragma unroll
        for (int q = 0; q < 8; q++) {
            int lin = t + 256 * q;
            int row = lin >> 5;
            int kk  = lin & 31;
            xs[kk][row] = X[(size_t)(i0 + row) * KK + c0 + kk];
        }
        __syncthreads();
#pragma unroll
        for (int kk = 0; kk < 32; kk++) {
            float4 w4 = *(const float4*)&W[(size_t)(c0 + kk) * FF + 4 * tx];
            unsigned long long w01 = pk2(w4.x, w4.y);
            unsigned long long w23 = pk2(w4.z, w4.w);
            float4 a4 = *(const float4*)&xs[kk][4 * ty];
            float av[4] = {a4.x, a4.y, a4.z, a4.w};
#pragma unroll
            for (int r = 0; r < 4; r++) {
                unsigned long long ar = pk2(av[r], av[r]);
                fma2(acc[r][0], ar, w01);
                fma2(acc[r][1], ar, w23);
            }
        }
        __syncthreads();
    }
#pragma unroll
    for (int r = 0; r < 4; r++) {
        float2 lo = upk(acc[r][0]);
        float2 hi = upk(acc[r][1]);
        *(float4*)&g_h[(size_t)(i0 + 4 * ty + r) * FF + 4 * tx] =
            make_float4(lo.x, lo.y, hi.x, hi.y);
    }
}

// =====================================================================
// B: hl = h @ a[:64], hr = h @ a[64:128]
// =====================================================================
__global__ void __launch_bounds__(256) k_hlr(const float* __restrict__ a) {
    __shared__ float a1s[FF], a2s[FF];
    const int t = threadIdx.x;
    if (t < FF)          a1s[t]      = a[t];
    else if (t < 2 * FF) a2s[t - FF] = a[t];
    __syncthreads();
    const int row = blockIdx.x * 256 + t;
    float s1 = 0.f, s2 = 0.f;
#pragma unroll
    for (int q = 0; q < 16; q++) {
        float4 h4 = *(const float4*)&g_h[(size_t)row * FF + 4 * q];
        s1 = fmaf(h4.x, a1s[4 * q + 0], s1);
        s1 = fmaf(h4.y, a1s[4 * q + 1], s1);
        s1 = fmaf(h4.z, a1s[4 * q + 2], s1);
        s1 = fmaf(h4.w, a1s[4 * q + 3], s1);
        s2 = fmaf(h4.x, a2s[4 * q + 0], s2);
        s2 = fmaf(h4.y, a2s[4 * q + 1], s2);
        s2 = fmaf(h4.z, a2s[4 * q + 2], s2);
        s2 = fmaf(h4.w, a2s[4 * q + 3], s2);
    }
    g_hl[row] = s1;
    g_hr[row] = s2;
}

// =====================================================================
// C: scalars
// =====================================================================
__global__ void k_scalars(const float* __restrict__ Wsi, const float* __restrict__ Wei) {
    __shared__ float red[256];
    const int t = threadIdx.x;
    float m = -3.4e38f;
    for (int i = t; i < NN; i += 256) m = fmaxf(m, g_hr[i]);
    red[t] = m;
    __syncthreads();
    for (int s = 128; s > 0; s >>= 1) {
        if (t < s) red[t] = fmaxf(red[t], red[t + s]);
        __syncthreads();
    }
    if (t == 0) {
        g_scalars[0] = red[0];
        g_scalars[1] = fabsf(Wei[0]);
        g_scalars[2] = fabsf(Wsi[0]);
    }
}

// =====================================================================
// D: fused attention, cp.async double-buffered pipeline.
// CTA = 64 rows x 1024 cols (16 tiles of 64 j), 256 threads, 2 CTAs/SM.
// =====================================================================
__device__ __forceinline__ void prefetch_adaj(const float* __restrict__ adj_ad,
                                              const int* __restrict__ adj,
                                              int i0, int j0, int t,
                                              float* ad_dst, int* aj_dst) {
#pragma unroll
    for (int q = 0; q < 4; q++) {
        int c  = q * 256 + t;       // 16B chunk id, 0..1023
        int r  = c >> 4;            // row 0..63
        int c4 = (c & 15) * 4;      // col float
        cpasync16(ad_dst + r * 64 + c4, adj_ad + (size_t)(i0 + r) * NN + j0 + c4);
        cpasync16(aj_dst + r * 64 + c4, adj    + (size_t)(i0 + r) * NN + j0 + c4);
    }
}

__global__ void __launch_bounds__(256, 2) k_attn(const float* __restrict__ adj_ad,
                                                 const int* __restrict__ adj) {
    extern __shared__ float smem[];
    float* ad_s = smem;                      // 2 * 4096
    int*   aj_s = (int*)(ad_s + 2 * 4096);   // 2 * 4096
    float* p_s  = (float*)(aj_s + 2 * 4096); // 64*68 = 4352
    float* h_s  = p_s + BI * PSTRIDE;        // 4096
    float* hl_s = h_s + BJ * FF;             // 64
    float* m_s  = hl_s + BI;                 // 64
    float* hr_s = m_s + BI;                  // 2*64

    const int t     = threadIdx.x;
    const int i0    = blockIdx.x * BI;
    const int split = blockIdx.y;
    const int j0b   = split * JCHUNK;

    const float hrmax = g_scalars[0];
    const float wei   = g_scalars[1];
    const float wsi   = g_scalars[2];

    if (t < BI) {
        float hl = g_hl[i0 + t];
        hl_s[t] = hl;
        float s  = hl + hrmax;
        float lr = fmaxf(s, 0.2f * s);
        m_s[t] = fmaf(wei, lr, wsi);         // row-i logit upper bound
    }
    if (t < 16) *(float4*)&hr_s[4 * t] = *(const float4*)&g_hr[j0b + 4 * t];

    // prologue: tile 0 in flight
    prefetch_adaj(adj_ad, adj, i0, j0b, t, ad_s, aj_s);
    CP_COMMIT();
    float4 hreg[4];
#pragma unroll
    for (int q = 0; q < 4; q++)
        hreg[q] = *(const float4*)&g_h[(size_t)j0b * FF + 4 * (q * 256 + t)];

    // phase-1 mapping: one row, 16 consecutive j per thread
    const int rw1 = t >> 2, q1 = t & 3;
    // phase-2 mapping: 4 rows x 8 f per thread, j-range split across halves
    const int tx2 = t & 7, ty2 = (t >> 3) & 15, half = t >> 7;

    unsigned long long acc[4][4];
#pragma unroll
    for (int r = 0; r < 4; r++)
#pragma unroll
        for (int c = 0; c < 4; c++) acc[r][c] = 0ULL;
    float zl = 0.f;

    for (int jt = 0; jt < NTILES; jt++) {
        const int jn  = (jt + 1 < NTILES) ? jt + 1 : NTILES - 1;
        const int j0n = j0b + jn * BJ;
        const int cur = jt & 1, nxt = (jt + 1) & 1;

        prefetch_adaj(adj_ad, adj, i0, j0n, t, ad_s + nxt * 4096, aj_s + nxt * 4096);
        CP_COMMIT();
        CP_WAIT1();                 // tile jt's ad/aj landed
        __syncthreads();            // + phase 2 of jt-1 done with p_s/h_s

        // stage h tile jt (from regs) and hr for jt+1
#pragma unroll
        for (int q = 0; q < 4; q++)
            *(float4*)&h_s[4 * (q * 256 + t)] = hreg[q];
        if (t < 16)
            *(float4*)&hr_s[nxt * 64 + 4 * t] = *(const float4*)&g_hr[j0n + 4 * t];

        // ---- phase 1: p tile from smem ad/aj ----
        {
            const float* adb = ad_s + cur * 4096 + rw1 * 64 + q1 * 16;
            const int*   ajb = aj_s + cur * 4096 + rw1 * 64 + q1 * 16;
            const float* hrb = hr_s + cur * 64 + q1 * 16;
            const float  hl  = hl_s[rw1];
            const float  mm  = m_s[rw1];
            float*       pd  = p_s + rw1 * PSTRIDE + q1 * 16;
#pragma unroll
            for (int k = 0; k < 4; k++) {
                float4 ad4 = *(const float4*)(adb + 4 * k);
                int4   aj4 = *(const int4*)(ajb + 4 * k);
                float4 hr4 = *(const float4*)(hrb + 4 * k);
                float4 p4;
                {
                    float s = hl + hr4.x, lr = fmaxf(s, 0.2f * s);
                    p4.x = (aj4.x > 0) ? __expf(fmaf(wei, lr, wsi * ad4.x) - mm) : 0.f;
                }
                {
                    float s = hl + hr4.y, lr = fmaxf(s, 0.2f * s);
                    p4.y = (aj4.y > 0) ? __expf(fmaf(wei, lr, wsi * ad4.y) - mm) : 0.f;
                }
                {
                    float s = hl + hr4.z, lr = fmaxf(s, 0.2f * s);
                    p4.z = (aj4.z > 0) ? __expf(fmaf(wei, lr, wsi * ad4.z) - mm) : 0.f;
                }
                {
                    float s = hl + hr4.w, lr = fmaxf(s, 0.2f * s);
                    p4.w = (aj4.w > 0) ? __expf(fmaf(wei, lr, wsi * ad4.w) - mm) : 0.f;
                }
                *(float4*)(pd + 4 * k) = p4;
                zl += (p4.x + p4.y) + (p4.z + p4.w);
            }
        }

        // prefetch h tile jt+1 into regs (contiguous 16KB, L2-resident)
#pragma unroll
        for (int q = 0; q < 4; q++)
            hreg[q] = *(const float4*)&g_h[(size_t)j0n * FF + 4 * (q * 256 + t)];

        __syncthreads();

        // ---- phase 2: acc += p @ h (this thread's half of j) ----
#pragma unroll
        for (int jb8 = 0; jb8 < 8; jb8++) {
            const int jb = half * 8 + jb8;
            float4 pr[4];
#pragma unroll
            for (int r = 0; r < 4; r++)
                pr[r] = *(const float4*)&p_s[(4 * ty2 + r) * PSTRIDE + 4 * jb];
#pragma unroll
            for (int jj = 0; jj < 4; jj++) {
                const float* hrow = &h_s[(4 * jb + jj) * FF + 8 * tx2];
                unsigned long long h01, h23, h45, h67;
                lds_u64x2(h01, h23, hrow);
                lds_u64x2(h45, h67, hrow + 4);
#pragma unroll
                for (int r = 0; r < 4; r++) {
                    float pv = (jj == 0) ? pr[r].x :
                               (jj == 1) ? pr[r].y :
                               (jj == 2) ? pr[r].z : pr[r].w;
                    unsigned long long pp = pk2(pv, pv);
                    fma2(acc[r][0], pp, h01);
                    fma2(acc[r][1], pp, h23);
                    fma2(acc[r][2], pp, h45);
                    fma2(acc[r][3], pp, h67);
                }
            }
        }
        // NOTE: no trailing sync needed; next iter's sync1 protects p_s/h_s
    }
    CP_WAITALL();

    // ---- z writeout (phase-1 mapping: reduce the 4 quads of each row) ----
    zl += __shfl_xor_sync(0xffffffffu, zl, 1);
    zl += __shfl_xor_sync(0xffffffffu, zl, 2);
    if (q1 == 0) g_Z[split * NN + i0 + rw1] = zl;

    // ---- merge halves through h_s, write partial numerators ----
    __syncthreads();
    if (half) {
#pragma unroll
        for (int r = 0; r < 4; r++) {
            float2 v0 = upk(acc[r][0]), v1 = upk(acc[r][1]);
            float2 v2 = upk(acc[r][2]), v3 = upk(acc[r][3]);
            float* dst = &h_s[(4 * ty2 + r) * FF + 8 * tx2];
            *(float4*)dst       = make_float4(v0.x, v0.y, v1.x, v1.y);
            *(float4*)(dst + 4) = make_float4(v2.x, v2.y, v3.x, v3.y);
        }
    }
    __syncthreads();
    if (!half) {
#pragma unroll
        for (int r = 0; r < 4; r++) {
            const float* src = &h_s[(4 * ty2 + r) * FF + 8 * tx2];
            float4 o0 = *(const float4*)src;
            float4 o1 = *(const float4*)(src + 4);
            float2 v0 = upk(acc[r][0]), v1 = upk(acc[r][1]);
            float2 v2 = upk(acc[r][2]), v3 = upk(acc[r][3]);
            const size_t base =
                ((size_t)split * NN + i0 + 4 * ty2 + r) * FF + 8 * tx2;
            *(float4*)&g_acc[base] =
                make_float4(v0.x + o0.x, v0.y + o0.y, v1.x + o0.z, v1.y + o0.w);
            *(float4*)&g_acc[base + 4] =
                make_float4(v2.x + o1.x, v2.y + o1.y, v3.x + o1.z, v3.y + o1.w);
        }
    }
}

// =====================================================================
// E: combine splits, normalize, ELU
// =====================================================================
__global__ void __launch_bounds__(256) k_combine(float* __restrict__ out) {
    const int idx = blockIdx.x * 256 + threadIdx.x;
    const int i   = idx >> 6;
    float num = 0.f, den = 0.f;
#pragma unroll
    for (int s = 0; s < SPLITJ; s++) {
        num += g_acc[(size_t)s * NN * FF + idx];
        den += g_Z[s * NN + i];
    }
    float r = num / den;
    out[idx] = (r > 0.0f) ? r : expm1f(r);
}

// =====================================================================
extern "C" void kernel_launch(void* const* d_in, const int* in_sizes, int n_in,
                              void* d_out, int out_size) {
    (void)in_sizes; (void)n_in; (void)out_size;
    const float* input  = (const float*)d_in[0];
    const float* W      = (const float*)d_in[1];
    const float* a      = (const float*)d_in[2];
    const float* W_si   = (const float*)d_in[3];
    const float* W_ei   = (const float*)d_in[4];
    const float* adj_ad = (const float*)d_in[5];
    const int*   adj    = (const int*)d_in[6];
    float* out = (float*)d_out;

    const int SMEM_D = (2 * 4096 + 2 * 4096 + BI * PSTRIDE + BJ * FF +
                        2 * BI + 2 * BJ) * (int)sizeof(float);   // 100352 B
    cudaFuncSetAttribute(k_attn, cudaFuncAttributeMaxDynamicSharedMemorySize, SMEM_D);

    k_gemm_h<<<NN / 64, 256>>>(input, W);
    k_hlr<<<NN / 256, 256>>>(a);
    k_scalars<<<1, 256>>>(W_si, W_ei);
    k_attn<<<dim3(NN / BI, SPLITJ), 256, SMEM_D>>>(adj_ad, adj);
    k_combine<<<NN * FF / 256, 256>>>(out);
}

// round 6
// speedup vs baseline: 1.4536x; 1.0015x over previous
#include <cuda_runtime.h>
#include <math.h>

#define NN 8192
#define KK 512
#define FF 64
#define SPLITJ 8
#define JCHUNK (NN / SPLITJ)   // 1024
#define BI 64
#define BJ 64
#define NTILES (JCHUNK / BJ)   // 16
#define PSTRIDE 68

// ---------------- device scratch (no cudaMalloc allowed) ----------------
__device__ float g_h[(size_t)NN * FF];                 // 2 MB
__device__ float g_hl[NN];
__device__ float g_hr[NN];
__device__ float g_scalars[4];                         // [0]=max(hr) [1]=|W_ei| [2]=|W_si|
__device__ float g_acc[(size_t)SPLITJ * NN * FF];      // 16 MB
__device__ float g_Z[SPLITJ * NN];

// ---------------- PTX helpers ----------------
__device__ __forceinline__ unsigned long long pk2(float x, float y) {
    unsigned long long r;
    asm("mov.b64 %0, {%1,%2};" : "=l"(r) : "f"(x), "f"(y));
    return r;
}
__device__ __forceinline__ void fma2(unsigned long long& d, unsigned long long a,
                                     unsigned long long b) {
    asm("fma.rn.f32x2 %0, %1, %2, %0;" : "+l"(d) : "l"(a), "l"(b));
}
__device__ __forceinline__ float2 upk(unsigned long long v) {
    float2 f;
    asm("mov.b64 {%0,%1}, %2;" : "=f"(f.x), "=f"(f.y) : "l"(v));
    return f;
}
// 128-bit shared load directly into two packed-f32x2 operands (no repack movs)
__device__ __forceinline__ void lds_u64x2(unsigned long long& a, unsigned long long& b,
                                          const float* p) {
    asm volatile("ld.shared.v2.u64 {%0,%1}, [%2];"
                 : "=l"(a), "=l"(b)
                 : "r"((unsigned)__cvta_generic_to_shared(p)));
}
__device__ __forceinline__ void cpasync16(void* dst_smem, const void* src) {
    asm volatile("cp.async.cg.shared.global [%0], [%1], 16;"
                 :: "r"((unsigned)__cvta_generic_to_shared(dst_smem)), "l"(src));
}
#define CP_COMMIT() asm volatile("cp.async.commit_group;" ::: "memory")
#define CP_WAIT1()  asm volatile("cp.async.wait_group 1;" ::: "memory")
#define CP_WAITALL() asm volatile("cp.async.wait_all;" ::: "memory")

// =====================================================================
// A: h = input @ W   [8192,512]x[512,64]. 64x64 tile, 256 thr, 4x4/thr.
// =====================================================================
__global__ void __launch_bounds__(256) k_gemm_h(const float* __restrict__ X,
                                                const float* __restrict__ W) {
    __shared__ float xs[32][68];
    const int t  = threadIdx.x;
    const int tx = t & 15;
    const int ty = t >> 4;
    const int i0 = blockIdx.x * 64;

    unsigned long long acc[4][2];
#pragma unroll
    for (int r = 0; r < 4; r++) { acc[r][0] = 0ULL; acc[r][1] = 0ULL; }

    for (int c0 = 0; c0 < KK; c0 += 32) {
#pragma unroll
        for (int q = 0; q < 8; q++) {
            int lin = t + 256 * q;
            int row = lin >> 5;
            int kk  = lin & 31;
            xs[kk][row] = X[(size_t)(i0 + row) * KK + c0 + kk];
        }
        __syncthreads();
#pragma unroll
        for (int kk = 0; kk < 32; kk++) {
            float4 w4 = *(const float4*)&W[(size_t)(c0 + kk) * FF + 4 * tx];
            unsigned long long w01 = pk2(w4.x, w4.y);
            unsigned long long w23 = pk2(w4.z, w4.w);
            float4 a4 = *(const float4*)&xs[kk][4 * ty];
            float av[4] = {a4.x, a4.y, a4.z, a4.w};
#pragma unroll
            for (int r = 0; r < 4; r++) {
                unsigned long long ar = pk2(av[r], av[r]);
                fma2(acc[r][0], ar, w01);
                fma2(acc[r][1], ar, w23);
            }
        }
        __syncthreads();
    }
#pragma unroll
    for (int r = 0; r < 4; r++) {
        float2 lo = upk(acc[r][0]);
        float2 hi = upk(acc[r][1]);
        *(float4*)&g_h[(size_t)(i0 + 4 * ty + r) * FF + 4 * tx] =
            make_float4(lo.x, lo.y, hi.x, hi.y);
    }
}

// =====================================================================
// B: hl = h @ a[:64], hr = h @ a[64:128]
// =====================================================================
__global__ void __launch_bounds__(256) k_hlr(const float* __restrict__ a) {
    __shared__ float a1s[FF], a2s[FF];
    const int t = threadIdx.x;
    if (t < FF)          a1s[t]      = a[t];
    else if (t < 2 * FF) a2s[t - FF] = a[t];
    __syncthreads();
    const int row = blockIdx.x * 256 + t;
    float s1 = 0.f, s2 = 0.f;
#pragma unroll
    for (int q = 0; q < 16; q++) {
        float4 h4 = *(const float4*)&g_h[(size_t)row * FF + 4 * q];
        s1 = fmaf(h4.x, a1s[4 * q + 0], s1);
        s1 = fmaf(h4.y, a1s[4 * q + 1], s1);
        s1 = fmaf(h4.z, a1s[4 * q + 2], s1);
        s1 = fmaf(h4.w, a1s[4 * q + 3], s1);
        s2 = fmaf(h4.x, a2s[4 * q + 0], s2);
        s2 = fmaf(h4.y, a2s[4 * q + 1], s2);
        s2 = fmaf(h4.z, a2s[4 * q + 2], s2);
        s2 = fmaf(h4.w, a2s[4 * q + 3], s2);
    }
    g_hl[row] = s1;
    g_hr[row] = s2;
}

// =====================================================================
// C: scalars
// =====================================================================
__global__ void k_scalars(const float* __restrict__ Wsi, const float* __restrict__ Wei) {
    __shared__ float red[256];
    const int t = threadIdx.x;
    float m = -3.4e38f;
    for (int i = t; i < NN; i += 256) m = fmaxf(m, g_hr[i]);
    red[t] = m;
    __syncthreads();
    for (int s = 128; s > 0; s >>= 1) {
        if (t < s) red[t] = fmaxf(red[t], red[t + s]);
        __syncthreads();
    }
    if (t == 0) {
        g_scalars[0] = red[0];
        g_scalars[1] = fabsf(Wei[0]);
        g_scalars[2] = fabsf(Wsi[0]);
    }
}

// =====================================================================
// D: fused attention, cp.async double-buffered pipeline.
// CTA = 64 rows x 1024 cols (16 tiles of 64 j), 256 threads, 2 CTAs/SM.
// =====================================================================
__device__ __forceinline__ void prefetch_adaj(const float* __restrict__ adj_ad,
                                              const int* __restrict__ adj,
                                              int i0, int j0, int t,
                                              float* ad_dst, int* aj_dst) {
#pragma unroll
    for (int q = 0; q < 4; q++) {
        int c  = q * 256 + t;       // 16B chunk id, 0..1023
        int r  = c >> 4;            // row 0..63
        int c4 = (c & 15) * 4;      // col float
        cpasync16(ad_dst + r * 64 + c4, adj_ad + (size_t)(i0 + r) * NN + j0 + c4);
        cpasync16(aj_dst + r * 64 + c4, adj    + (size_t)(i0 + r) * NN + j0 + c4);
    }
}

__global__ void __launch_bounds__(256, 2) k_attn(const float* __restrict__ adj_ad,
                                                 const int* __restrict__ adj) {
    extern __shared__ float smem[];
    float* ad_s = smem;                      // 2 * 4096
    int*   aj_s = (int*)(ad_s + 2 * 4096);   // 2 * 4096
    float* p_s  = (float*)(aj_s + 2 * 4096); // 64*68 = 4352
    float* h_s  = p_s + BI * PSTRIDE;        // 4096
    float* hl_s = h_s + BJ * FF;             // 64
    float* m_s  = hl_s + BI;                 // 64
    float* hr_s = m_s + BI;                  // 2*64

    const int t     = threadIdx.x;
    const int i0    = blockIdx.x * BI;
    const int split = blockIdx.y;
    const int j0b   = split * JCHUNK;

    const float hrmax = g_scalars[0];
    const float wei   = g_scalars[1];
    const float wsi   = g_scalars[2];

    if (t < BI) {
        float hl = g_hl[i0 + t];
        hl_s[t] = hl;
        float s  = hl + hrmax;
        float lr = fmaxf(s, 0.2f * s);
        m_s[t] = fmaf(wei, lr, wsi);         // row-i logit upper bound
    }
    if (t < 16) *(float4*)&hr_s[4 * t] = *(const float4*)&g_hr[j0b + 4 * t];

    // prologue: tile 0 in flight
    prefetch_adaj(adj_ad, adj, i0, j0b, t, ad_s, aj_s);
    CP_COMMIT();
    float4 hreg[4];
#pragma unroll
    for (int q = 0; q < 4; q++)
        hreg[q] = *(const float4*)&g_h[(size_t)j0b * FF + 4 * (q * 256 + t)];

    // phase-1 mapping: one row, 16 consecutive j per thread
    const int rw1 = t >> 2, q1 = t & 3;
    // phase-2 mapping: 4 rows x 8 f per thread, j-range split across halves
    const int tx2 = t & 7, ty2 = (t >> 3) & 15, half = t >> 7;

    unsigned long long acc[4][4];
#pragma unroll
    for (int r = 0; r < 4; r++)
#pragma unroll
        for (int c = 0; c < 4; c++) acc[r][c] = 0ULL;
    float zl = 0.f;

    for (int jt = 0; jt < NTILES; jt++) {
        const int jn  = (jt + 1 < NTILES) ? jt + 1 : NTILES - 1;
        const int j0n = j0b + jn * BJ;
        const int cur = jt & 1, nxt = (jt + 1) & 1;

        prefetch_adaj(adj_ad, adj, i0, j0n, t, ad_s + nxt * 4096, aj_s + nxt * 4096);
        CP_COMMIT();
        CP_WAIT1();                 // tile jt's ad/aj landed
        __syncthreads();            // + phase 2 of jt-1 done with p_s/h_s

        // stage h tile jt (from regs) and hr for jt+1
#pragma unroll
        for (int q = 0; q < 4; q++)
            *(float4*)&h_s[4 * (q * 256 + t)] = hreg[q];
        if (t < 16)
            *(float4*)&hr_s[nxt * 64 + 4 * t] = *(const float4*)&g_hr[j0n + 4 * t];

        // ---- phase 1: p tile from smem ad/aj ----
        {
            const float* adb = ad_s + cur * 4096 + rw1 * 64 + q1 * 16;
            const int*   ajb = aj_s + cur * 4096 + rw1 * 64 + q1 * 16;
            const float* hrb = hr_s + cur * 64 + q1 * 16;
            const float  hl  = hl_s[rw1];
            const float  mm  = m_s[rw1];
            float*       pd  = p_s + rw1 * PSTRIDE + q1 * 16;
#pragma unroll
            for (int k = 0; k < 4; k++) {
                float4 ad4 = *(const float4*)(adb + 4 * k);
                int4   aj4 = *(const int4*)(ajb + 4 * k);
                float4 hr4 = *(const float4*)(hrb + 4 * k);
                float4 p4;
                {
                    float s = hl + hr4.x, lr = fmaxf(s, 0.2f * s);
                    p4.x = (aj4.x > 0) ? __expf(fmaf(wei, lr, wsi * ad4.x) - mm) : 0.f;
                }
                {
                    float s = hl + hr4.y, lr = fmaxf(s, 0.2f * s);
                    p4.y = (aj4.y > 0) ? __expf(fmaf(wei, lr, wsi * ad4.y) - mm) : 0.f;
                }
                {
                    float s = hl + hr4.z, lr = fmaxf(s, 0.2f * s);
                    p4.z = (aj4.z > 0) ? __expf(fmaf(wei, lr, wsi * ad4.z) - mm) : 0.f;
                }
                {
                    float s = hl + hr4.w, lr = fmaxf(s, 0.2f * s);
                    p4.w = (aj4.w > 0) ? __expf(fmaf(wei, lr, wsi * ad4.w) - mm) : 0.f;
                }
                *(float4*)(pd + 4 * k) = p4;
                zl += (p4.x + p4.y) + (p4.z + p4.w);
            }
        }

        // prefetch h tile jt+1 into regs (contiguous 16KB, L2-resident)
#pragma unroll
        for (int q = 0; q < 4; q++)
            hreg[q] = *(const float4*)&g_h[(size_t)j0n * FF + 4 * (q * 256 + t)];

        __syncthreads();

        // ---- phase 2: acc += p @ h (this thread's half of j) ----
#pragma unroll
        for (int jb8 = 0; jb8 < 8; jb8++) {
            const int jb = half * 8 + jb8;
            float4 pr[4];
#pragma unroll
            for (int r = 0; r < 4; r++)
                pr[r] = *(const float4*)&p_s[(4 * ty2 + r) * PSTRIDE + 4 * jb];
#pragma unroll
            for (int jj = 0; jj < 4; jj++) {
                const float* hrow = &h_s[(4 * jb + jj) * FF + 8 * tx2];
                unsigned long long h01, h23, h45, h67;
                lds_u64x2(h01, h23, hrow);
                lds_u64x2(h45, h67, hrow + 4);
#pragma unroll
                for (int r = 0; r < 4; r++) {
                    float pv = (jj == 0) ? pr[r].x :
                               (jj == 1) ? pr[r].y :
                               (jj == 2) ? pr[r].z : pr[r].w;
                    unsigned long long pp = pk2(pv, pv);
                    fma2(acc[r][0], pp, h01);
                    fma2(acc[r][1], pp, h23);
                    fma2(acc[r][2], pp, h45);
                    fma2(acc[r][3], pp, h67);
                }
            }
        }
        // NOTE: no trailing sync needed; next iter's sync1 protects p_s/h_s
    }
    CP_WAITALL();

    // ---- z writeout (phase-1 mapping: reduce the 4 quads of each row) ----
    zl += __shfl_xor_sync(0xffffffffu, zl, 1);
    zl += __shfl_xor_sync(0xffffffffu, zl, 2);
    if (q1 == 0) g_Z[split * NN + i0 + rw1] = zl;

    // ---- merge halves through h_s, write partial numerators ----
    __syncthreads();
    if (half) {
#pragma unroll
        for (int r = 0; r < 4; r++) {
            float2 v0 = upk(acc[r][0]), v1 = upk(acc[r][1]);
            float2 v2 = upk(acc[r][2]), v3 = upk(acc[r][3]);
            float* dst = &h_s[(4 * ty2 + r) * FF + 8 * tx2];
            *(float4*)dst       = make_float4(v0.x, v0.y, v1.x, v1.y);
            *(float4*)(dst + 4) = make_float4(v2.x, v2.y, v3.x, v3.y);
        }
    }
    __syncthreads();
    if (!half) {
#pragma unroll
        for (int r = 0; r < 4; r++) {
            const float* src = &h_s[(4 * ty2 + r) * FF + 8 * tx2];
            float4 o0 = *(const float4*)src;
            float4 o1 = *(const float4*)(src + 4);
            float2 v0 = upk(acc[r][0]), v1 = upk(acc[r][1]);
            float2 v2 = upk(acc[r][2]), v3 = upk(acc[r][3]);
            const size_t base =
                ((size_t)split * NN + i0 + 4 * ty2 + r) * FF + 8 * tx2;
            *(float4*)&g_acc[base] =
                make_float4(v0.x + o0.x, v0.y + o0.y, v1.x + o0.z, v1.y + o0.w);
            *(float4*)&g_acc[base + 4] =
                make_float4(v2.x + o1.x, v2.y + o1.y, v3.x + o1.z, v3.y + o1.w);
        }
    }
}

// =====================================================================
// E: combine splits, normalize, ELU
// =====================================================================
__global__ void __launch_bounds__(256) k_combine(float* __restrict__ out) {
    const int idx = blockIdx.x * 256 + threadIdx.x;
    const int i   = idx >> 6;
    float num = 0.f, den = 0.f;
#pragma unroll
    for (int s = 0; s < SPLITJ; s++) {
        num += g_acc[(size_t)s * NN * FF + idx];
        den += g_Z[s * NN + i];
    }
    float r = num / den;
    out[idx] = (r > 0.0f) ? r : expm1f(r);
}

// =====================================================================
extern "C" void kernel_launch(void* const* d_in, const int* in_sizes, int n_in,
                              void* d_out, int out_size) {
    (void)in_sizes; (void)n_in; (void)out_size;
    const float* input  = (const float*)d_in[0];
    const float* W      = (const float*)d_in[1];
    const float* a      = (const float*)d_in[2];
    const float* W_si   = (const float*)d_in[3];
    const float* W_ei   = (const float*)d_in[4];
    const float* adj_ad = (const float*)d_in[5];
    const int*   adj    = (const int*)d_in[6];
    float* out = (float*)d_out;

    const int SMEM_D = (2 * 4096 + 2 * 4096 + BI * PSTRIDE + BJ * FF +
                        2 * BI + 2 * BJ) * (int)sizeof(float);   // 100352 B
    cudaFuncSetAttribute(k_attn, cudaFuncAttributeMaxDynamicSharedMemorySize, SMEM_D);

    k_gemm_h<<<NN / 64, 256>>>(input, W);
    k_hlr<<<NN / 256, 256>>>(a);
    k_scalars<<<1, 256>>>(W_si, W_ei);
    k_attn<<<dim3(NN / BI, SPLITJ), 256, SMEM_D>>>(adj_ad, adj);
    k_combine<<<NN * FF / 256, 256>>>(out);
}

// round 8
// speedup vs baseline: 2.6086x; 1.7946x over previous
#include <cuda_runtime.h>
#include <math.h>
#include <stdint.h>

#define NN 8192
#define KK 512
#define FF 64
#define SPLITJ 8
#define JCHUNK (NN / SPLITJ)   // 1024
#define BI 64
#define BJ 64
#define NT (JCHUNK / BJ)       // 16

// smem layout (bytes), 16B-aligned base
#define ADSTG 17408            // 64 rows * 272B (68-float padded stride)
#define SM_AD 0                // 2 stages
#define SM_AJ (SM_AD + 2 * ADSTG)
#define SM_P  (SM_AJ + 2 * ADSTG)   // Phi 9216 + Plo 9216 (144B row stride)
#define SM_HT (SM_P + 2 * 9216)     // Hthi 9216 + Htlo 9216
#define SM_HR (SM_HT + 2 * 9216)    // 4096
#define SM_BYTES (SM_HR + 4096)     // 110592

__device__ float g_h[(size_t)NN * FF];
__device__ float g_hl[NN];
__device__ float g_hr[NN];
__device__ float g_scalars[4];
__device__ uint32_t g_hT[2u * 64u * 4096u];          // [var][f][j/2] bf16x2, 2 MB
__device__ float g_acc[(size_t)SPLITJ * NN * FF];    // 16 MB
__device__ float g_Z[SPLITJ * NN];

// ---------- helpers ----------
__device__ __forceinline__ unsigned long long pk2(float x, float y) {
    unsigned long long r; asm("mov.b64 %0, {%1,%2};" : "=l"(r) : "f"(x), "f"(y)); return r;
}
__device__ __forceinline__ void fma2(unsigned long long& d, unsigned long long a, unsigned long long b) {
    asm("fma.rn.f32x2 %0, %1, %2, %0;" : "+l"(d) : "l"(a), "l"(b));
}
__device__ __forceinline__ float2 upk(unsigned long long v) {
    float2 f; asm("mov.b64 {%0,%1}, %2;" : "=f"(f.x), "=f"(f.y) : "l"(v)); return f;
}
__device__ __forceinline__ uint32_t smem_u32(const void* p) {
    uint32_t a; asm("{ .reg .u64 t; cvta.to.shared.u64 t, %1; cvt.u32.u64 %0, t; }" : "=r"(a) : "l"(p)); return a;
}
__device__ __forceinline__ void cpa16(uint32_t dst, const void* src) {
    asm volatile("cp.async.cg.shared.global [%0], [%1], 16;" :: "r"(dst), "l"(src));
}
#define CP_COMMIT()  asm volatile("cp.async.commit_group;" ::: "memory")
#define CP_WAIT1()   asm volatile("cp.async.wait_group 1;" ::: "memory")
#define CP_WAITALL() asm volatile("cp.async.wait_all;" ::: "memory")

__device__ __forceinline__ uint32_t bf16x2_of(float lo, float hi) {
    uint32_t r; asm("cvt.rn.bf16x2.f32 %0, %1, %2;" : "=r"(r) : "f"(hi), "f"(lo)); return r;
}
__device__ __forceinline__ void ldm4(uint32_t* r, uint32_t addr) {
    asm volatile("ldmatrix.sync.aligned.m8n8.x4.shared.b16 {%0,%1,%2,%3}, [%4];"
                 : "=r"(r[0]), "=r"(r[1]), "=r"(r[2]), "=r"(r[3]) : "r"(addr));
}
__device__ __forceinline__ void mma16816(float* d, const uint32_t* a, uint32_t b0, uint32_t b1) {
    asm volatile("mma.sync.aligned.m16n8k16.row.col.f32.bf16.bf16.f32 "
                 "{%0,%1,%2,%3}, {%4,%5,%6,%7}, {%8,%9}, {%0,%1,%2,%3};"
                 : "+f"(d[0]), "+f"(d[1]), "+f"(d[2]), "+f"(d[3])
                 : "r"(a[0]), "r"(a[1]), "r"(a[2]), "r"(a[3]), "r"(b0), "r"(b1));
}

// ============ A: h = input @ W ============
__global__ void __launch_bounds__(256) k_gemm_h(const float* __restrict__ X, const float* __restrict__ W) {
    __shared__ float xs[32][68];
    const int t = threadIdx.x, tx = t & 15, ty = t >> 4, i0 = blockIdx.x * 64;
    unsigned long long acc[4][2];
#pragma unroll
    for (int r = 0; r < 4; r++) { acc[r][0] = 0ULL; acc[r][1] = 0ULL; }
    for (int c0 = 0; c0 < KK; c0 += 32) {
#pragma unroll
        for (int q = 0; q < 8; q++) {
            int lin = t + 256 * q, row = lin >> 5, kk = lin & 31;
            xs[kk][row] = X[(size_t)(i0 + row) * KK + c0 + kk];
        }
        __syncthreads();
#pragma unroll
        for (int kk = 0; kk < 32; kk++) {
            float4 w4 = *(const float4*)&W[(size_t)(c0 + kk) * FF + 4 * tx];
            unsigned long long w01 = pk2(w4.x, w4.y), w23 = pk2(w4.z, w4.w);
            float4 a4 = *(const float4*)&xs[kk][4 * ty];
            float av[4] = {a4.x, a4.y, a4.z, a4.w};
#pragma unroll
            for (int r = 0; r < 4; r++) {
                unsigned long long ar = pk2(av[r], av[r]);
                fma2(acc[r][0], ar, w01); fma2(acc[r][1], ar, w23);
            }
        }
        __syncthreads();
    }
#pragma unroll
    for (int r = 0; r < 4; r++) {
        float2 lo = upk(acc[r][0]), hi = upk(acc[r][1]);
        *(float4*)&g_h[(size_t)(i0 + 4 * ty + r) * FF + 4 * tx] = make_float4(lo.x, lo.y, hi.x, hi.y);
    }
}

// ============ B: hl/hr ============
__global__ void __launch_bounds__(256) k_hlr(const float* __restrict__ a) {
    __shared__ float a1s[FF], a2s[FF];
    const int t = threadIdx.x;
    if (t < FF) a1s[t] = a[t]; else if (t < 2 * FF) a2s[t - FF] = a[t];
    __syncthreads();
    const int row = blockIdx.x * 256 + t;
    float s1 = 0.f, s2 = 0.f;
#pragma unroll
    for (int q = 0; q < 16; q++) {
        float4 h4 = *(const float4*)&g_h[(size_t)row * FF + 4 * q];
        s1 = fmaf(h4.x, a1s[4*q], fmaf(h4.y, a1s[4*q+1], fmaf(h4.z, a1s[4*q+2], fmaf(h4.w, a1s[4*q+3], s1))));
        s2 = fmaf(h4.x, a2s[4*q], fmaf(h4.y, a2s[4*q+1], fmaf(h4.z, a2s[4*q+2], fmaf(h4.w, a2s[4*q+3], s2))));
    }
    g_hl[row] = s1; g_hr[row] = s2;
}

// ============ C: scalars ============
__global__ void k_scalars(const float* __restrict__ Wsi, const float* __restrict__ Wei) {
    __shared__ float red[256];
    const int t = threadIdx.x;
    float m = -3.4e38f;
    for (int i = t; i < NN; i += 256) m = fmaxf(m, g_hr[i]);
    red[t] = m; __syncthreads();
    for (int s = 128; s > 0; s >>= 1) { if (t < s) red[t] = fmaxf(red[t], red[t + s]); __syncthreads(); }
    if (t == 0) { g_scalars[0] = red[0]; g_scalars[1] = fabsf(Wei[0]); g_scalars[2] = fabsf(Wsi[0]); }
}

// ============ Prep: H^T as [f][j] bf16 hi/lo ============
__global__ void __launch_bounds__(256) k_prep_ht() {
    __shared__ float hs[128 * 68];
    const int t = threadIdx.x, j0 = blockIdx.x * 128;
#pragma unroll
    for (int k = 0; k < 8; k++) {
        int i4 = k * 256 + t;              // float4 id 0..2047
        int j = i4 >> 4, f4 = i4 & 15;
        *(float4*)&hs[j * 68 + f4 * 4] = *(const float4*)&g_h[(size_t)(j0 + j) * FF + f4 * 4];
    }
    __syncthreads();
    const int f = t >> 2, jq = t & 3;
#pragma unroll
    for (int m = 0; m < 4; m++) {
        int jl = jq * 32 + m * 8;
        uint32_t hiv[4], lov[4];
#pragma unroll
        for (int s = 0; s < 4; s++) {
            float v0 = hs[(jl + 2 * s) * 68 + f], v1 = hs[(jl + 2 * s + 1) * 68 + f];
            uint32_t h2 = bf16x2_of(v0, v1);
            hiv[s] = h2;
            lov[s] = bf16x2_of(v0 - __uint_as_float(h2 << 16), v1 - __uint_as_float(h2 & 0xffff0000u));
        }
        uint32_t idx = (uint32_t)f * 4096u + (uint32_t)((j0 + jl) >> 1);
        *(uint4*)&g_hT[idx]           = make_uint4(hiv[0], hiv[1], hiv[2], hiv[3]);
        *(uint4*)&g_hT[262144u + idx] = make_uint4(lov[0], lov[1], lov[2], lov[3]);
    }
}

// ============ D: fused attention (mma.sync bf16 hi/lo split) ============
__device__ __forceinline__ void issue_adaj(const float* __restrict__ adj_ad, const int* __restrict__ adj,
                                           int i0, int j0, int t, uint32_t ad_dst, uint32_t aj_dst) {
#pragma unroll
    for (int k = 0; k < 4; k++) {
        int c = k * 256 + t, r = c >> 4, ch = c & 15;
        cpa16(ad_dst + r * 272 + ch * 16, adj_ad + (size_t)(i0 + r) * NN + j0 + ch * 4);
        cpa16(aj_dst + r * 272 + ch * 16, adj    + (size_t)(i0 + r) * NN + j0 + ch * 4);
    }
}

__global__ void __launch_bounds__(256, 2) k_attn(const float* __restrict__ adj_ad,
                                                 const int* __restrict__ adj) {
    extern __shared__ float4 smem4[];
    char* base = (char*)smem4;
    const uint32_t sb = smem_u32(base);

    const int t = threadIdx.x, wid = t >> 5, l = t & 31;
    const int i0 = blockIdx.x * BI, split = blockIdx.y, j0b = split * JCHUNK;

    // hr for whole JCHUNK
    *(float4*)(base + SM_HR + 16 * t) = *(const float4*)&g_hr[j0b + 4 * t];

    const float hrmax = g_scalars[0], wei = g_scalars[1], wsi = g_scalars[2];
    const int r1 = t >> 2, q1 = t & 3;                 // phase-1: row, j-quad
    const float hl_r = g_hl[i0 + r1];
    float smax = hl_r + hrmax;
    const float m_r = fmaf(wei, fmaxf(smax, 0.2f * smax), wsi);

    // phase-2 addressing (constant across tiles)
    const int iw = wid & 3, fh = wid >> 2;
    const uint32_t aRow = (uint32_t)((l & 7) | (l & 8));
    const uint32_t aOff = (uint32_t)(16 * iw + aRow) * 144u + (uint32_t)(((l >> 4) & 1) * 16);
    const uint32_t bRow = (uint32_t)(32 * fh + ((l & 7) | (((l >> 4) & 1) << 3)));
    const uint32_t bOff = bRow * 144u + (uint32_t)(((l >> 3) & 1) * 16);
    const uint32_t pHi = sb + SM_P + aOff,  pLo = pHi + 9216u;
    const uint32_t hH0 = sb + SM_HT + bOff, hH1 = hH0 + 16u * 144u;
    const uint32_t hL0 = hH0 + 9216u,       hL1 = hH1 + 9216u;

    float acc[16];
#pragma unroll
    for (int i = 0; i < 16; i++) acc[i] = 0.f;
    float zl = 0.f;

    // prologue: tile 0 adaj in flight, tile 0 Ht in regs
    issue_adaj(adj_ad, adj, i0, j0b, t, sb + SM_AD, sb + SM_AJ);
    CP_COMMIT();
    uint4 hreg[4];
#pragma unroll
    for (int k = 0; k < 4; k++) {
        int c = k * 256 + t, var = c >> 9, f = (c >> 3) & 63, ch = c & 7;
        hreg[k] = *(const uint4*)&g_hT[(uint32_t)var * 262144u + (uint32_t)f * 4096u +
                                       (uint32_t)(j0b >> 1) + (uint32_t)ch * 4u];
    }

    for (int jt = 0; jt < NT; jt++) {
        const int cst = jt & 1, nst = (jt + 1) & 1;
        const int jn = (jt + 1 < NT) ? jt + 1 : NT - 1;
        issue_adaj(adj_ad, adj, i0, j0b + jn * BJ, t, sb + SM_AD + nst * ADSTG, sb + SM_AJ + nst * ADSTG);
        CP_COMMIT();
        CP_WAIT1();
        __syncthreads();   // adaj[jt] visible to all; phase2[jt-1] done with P/Ht

        // ---- phase 1: p + bf16 split ----
        {
            const float* ads = (const float*)(base + SM_AD + cst * ADSTG) + r1 * 68 + q1 * 16;
            const int*   ajs = (const int*)  (base + SM_AJ + cst * ADSTG) + r1 * 68 + q1 * 16;
            const float* hrs = (const float*)(base + SM_HR) + jt * 64 + q1 * 16;
            uint32_t hiv[8], lov[8];
#pragma unroll
            for (int k = 0; k < 4; k++) {
                float4 ad4 = *(const float4*)(ads + 4 * k);
                int4   aj4 = *(const int4*)(ajs + 4 * k);
                float4 hr4 = *(const float4*)(hrs + 4 * k);
                float pv[4];
                {
                    float s = hl_r + hr4.x, lr = fmaxf(s, 0.2f * s);
                    pv[0] = (aj4.x > 0) ? __expf(fmaf(wei, lr, fmaf(wsi, ad4.x, -m_r))) : 0.f;
                }
                {
                    float s = hl_r + hr4.y, lr = fmaxf(s, 0.2f * s);
                    pv[1] = (aj4.y > 0) ? __expf(fmaf(wei, lr, fmaf(wsi, ad4.y, -m_r))) : 0.f;
                }
                {
                    float s = hl_r + hr4.z, lr = fmaxf(s, 0.2f * s);
                    pv[2] = (aj4.z > 0) ? __expf(fmaf(wei, lr, fmaf(wsi, ad4.z, -m_r))) : 0.f;
                }
                {
                    float s = hl_r + hr4.w, lr = fmaxf(s, 0.2f * s);
                    pv[3] = (aj4.w > 0) ? __expf(fmaf(wei, lr, fmaf(wsi, ad4.w, -m_r))) : 0.f;
                }
                zl += (pv[0] + pv[1]) + (pv[2] + pv[3]);
                uint32_t h0 = bf16x2_of(pv[0], pv[1]);
                uint32_t h1 = bf16x2_of(pv[2], pv[3]);
                hiv[2*k]   = h0;
                hiv[2*k+1] = h1;
                lov[2*k]   = bf16x2_of(pv[0] - __uint_as_float(h0 << 16), pv[1] - __uint_as_float(h0 & 0xffff0000u));
                lov[2*k+1] = bf16x2_of(pv[2] - __uint_as_float(h1 << 16), pv[3] - __uint_as_float(h1 & 0xffff0000u));
            }
            char* pb = base + SM_P + r1 * 144 + q1 * 32;
            *(uint4*)pb          = make_uint4(hiv[0], hiv[1], hiv[2], hiv[3]);
            *(uint4*)(pb + 16)   = make_uint4(hiv[4], hiv[5], hiv[6], hiv[7]);
            *(uint4*)(pb + 9216) = make_uint4(lov[0], lov[1], lov[2], lov[3]);
            *(uint4*)(pb + 9232) = make_uint4(lov[4], lov[5], lov[6], lov[7]);
        }

        // ---- stage Ht[jt] from regs, prefetch Ht[jt+1] ----
#pragma unroll
        for (int k = 0; k < 4; k++) {
            int c = k * 256 + t, var = c >> 9, f = (c >> 3) & 63, ch = c & 7;
            *(uint4*)(base + SM_HT + var * 9216 + f * 144 + ch * 16) = hreg[k];
        }
        if (jt + 1 < NT) {
#pragma unroll
            for (int k = 0; k < 4; k++) {
                int c = k * 256 + t, var = c >> 9, f = (c >> 3) & 63, ch = c & 7;
                hreg[k] = *(const uint4*)&g_hT[(uint32_t)var * 262144u + (uint32_t)f * 4096u +
                                               (uint32_t)((j0b + (jt + 1) * BJ) >> 1) + (uint32_t)ch * 4u];
            }
        }
        __syncthreads();   // P + Ht ready

        // ---- phase 2: mma ----
#pragma unroll
        for (int ks = 0; ks < 4; ks++) {
            const uint32_t ka = (uint32_t)ks * 32u;
            uint32_t ahi[4], alo[4], bh0[4], bh1[4], bl0[4], bl1[4];
            ldm4(ahi, pHi + ka);
            ldm4(alo, pLo + ka);
            ldm4(bh0, hH0 + ka);
            ldm4(bh1, hH1 + ka);
            ldm4(bl0, hL0 + ka);
            ldm4(bl1, hL1 + ka);
            mma16816(acc + 0,  ahi, bh0[0], bh0[1]);
            mma16816(acc + 0,  ahi, bl0[0], bl0[1]);
            mma16816(acc + 0,  alo, bh0[0], bh0[1]);
            mma16816(acc + 4,  ahi, bh0[2], bh0[3]);
            mma16816(acc + 4,  ahi, bl0[2], bl0[3]);
            mma16816(acc + 4,  alo, bh0[2], bh0[3]);
            mma16816(acc + 8,  ahi, bh1[0], bh1[1]);
            mma16816(acc + 8,  ahi, bl1[0], bl1[1]);
            mma16816(acc + 8,  alo, bh1[0], bh1[1]);
            mma16816(acc + 12, ahi, bh1[2], bh1[3]);
            mma16816(acc + 12, ahi, bl1[2], bl1[3]);
            mma16816(acc + 12, alo, bh1[2], bh1[3]);
        }
    }
    CP_WAITALL();

    // z writeout
    zl += __shfl_xor_sync(0xffffffffu, zl, 1);
    zl += __shfl_xor_sync(0xffffffffu, zl, 2);
    if (q1 == 0) g_Z[split * NN + i0 + r1] = zl;

    // acc writeout: warp (iw,fh), lane (g,tig)
    {
        const int g = l >> 2, tig = l & 3;
#pragma unroll
        for (int nt = 0; nt < 4; nt++) {
            const int col = 32 * fh + 8 * nt + 2 * tig;
            const size_t b0 = ((size_t)split * NN + i0 + 16 * iw + g) * FF + col;
            const size_t b1 = b0 + (size_t)8 * FF;
            *(float2*)&g_acc[b0] = make_float2(acc[4 * nt + 0], acc[4 * nt + 1]);
            *(float2*)&g_acc[b1] = make_float2(acc[4 * nt + 2], acc[4 * nt + 3]);
        }
    }
}

// ============ E: combine, normalize, ELU ============
__global__ void __launch_bounds__(256) k_combine(float* __restrict__ out) {
    const int idx = blockIdx.x * 256 + threadIdx.x;
    const int i = idx >> 6;
    float num = 0.f, den = 0.f;
#pragma unroll
    for (int s = 0; s < SPLITJ; s++) {
        num += g_acc[(size_t)s * NN * FF + idx];
        den += g_Z[s * NN + i];
    }
    float r = num / den;
    out[idx] = (r > 0.0f) ? r : expm1f(r);
}

extern "C" void kernel_launch(void* const* d_in, const int* in_sizes, int n_in,
                              void* d_out, int out_size) {
    (void)in_sizes; (void)n_in; (void)out_size;
    const float* input  = (const float*)d_in[0];
    const float* W      = (const float*)d_in[1];
    const float* a      = (const float*)d_in[2];
    const float* W_si   = (const float*)d_in[3];
    const float* W_ei   = (const float*)d_in[4];
    const float* adj_ad = (const float*)d_in[5];
    const int*   adj    = (const int*)d_in[6];
    float* out = (float*)d_out;

    cudaFuncSetAttribute(k_attn, cudaFuncAttributeMaxDynamicSharedMemorySize, SM_BYTES);

    k_gemm_h<<<NN / 64, 256>>>(input, W);
    k_hlr<<<NN / 256, 256>>>(a);
    k_scalars<<<1, 256>>>(W_si, W_ei);
    k_prep_ht<<<NN / 128, 256>>>();
    k_attn<<<dim3(NN / BI, SPLITJ), 256, SM_BYTES>>>(adj_ad, adj);
    k_combine<<<NN * FF / 256, 256>>>(out);
}